// round 15
// baseline (speedup 1.0000x reference)
#include <cuda_runtime.h>

#define NB 32      // batch
#define NT 2048    // tokens
#define ND 1024    // d_token == n_heads*d_head
#define ND4 (ND/4)
#define TS 16      // token splits in reduce
#define TOK (NT/TS)           // 128 tokens per reduce block
#define GRID 512   // 16 splits x 32 batch; ZERO smem, <=64 regs -> 4/SM

// Scratch (allocation-free: __device__ globals, zero-initialized)
__device__ float g_part[TS][NB * ND];     // reduce partials (2 MB)
__device__ float g_xs[NB * ND];           // folded token sum (128 KB)
__device__ float g_xh[NB * ND];           // gemm0 output (full-K, final)
__device__ unsigned g_cnt[3];             // barrier arrive counters (self-reset)
__device__ unsigned g_rel[3];             // barrier release generations (monotone)

// ---------------------------------------------------------------------------
// Grid barrier (generation-based, graph-replay-safe). 512 blocks, zero smem,
// 64 regs, 256 thr -> exactly 4 blocks/SM on 148 SMs: all co-resident.
// ---------------------------------------------------------------------------
__device__ __forceinline__ void grid_bar(int i) {
    __syncthreads();
    if (threadIdx.x == 0) {
        volatile unsigned* rel = &g_rel[i];
        const unsigned gen = *rel;          // read BEFORE our arrive
        __threadfence();                    // publish this block's phase writes
        if (atomicAdd(&g_cnt[i], 1u) == GRID - 1) {
            g_cnt[i] = 0;                   // reset for next graph replay
            __threadfence();
            atomicAdd(&g_rel[i], 1u);       // release (monotone)
        } else {
            while (*rel == gen) { __nanosleep(32); }
        }
        __threadfence();
    }
    __syncthreads();
}

// ---------------------------------------------------------------------------
// helpers
// ---------------------------------------------------------------------------
__device__ __forceinline__ void ffma2(unsigned long long& d,
                                      unsigned long long a,
                                      unsigned long long b) {
    asm("fma.rn.f32x2 %0, %1, %2, %0;" : "+l"(d) : "l"(a), "l"(b));
}
__device__ __forceinline__ float hsum2(unsigned long long v) {
    float2 f;
    __builtin_memcpy(&f, &v, 8);
    return f.x + f.y;
}
__device__ __forceinline__ float4 ldcs4(const float4* p) {   // streaming load
    float4 v;
    asm volatile("ld.global.cs.v4.f32 {%0,%1,%2,%3}, [%4];"
                 : "=f"(v.x), "=f"(v.y), "=f"(v.z), "=f"(v.w) : "l"(p));
    return v;
}
__device__ __forceinline__ void l2_prefetch(const void* p) {
    asm volatile("prefetch.global.L2 [%0];" :: "l"(p));
}

// ---------------------------------------------------------------------------
// Warp-level smem-free GEMM phase: dst[b, o] = <A[b,:], W[o,:]> (+ bias[o]).
// 4096 warps; warp gw owns column o = gw & 1023 and rows b0..b0+7,
// b0 = (gw >> 10) * 8. Lane covers K-slice [lane*32, lane*32+32).
// Loads straight from L2 (A just written, W resident). 8 ull accumulators,
// 23-shuffle matched butterfly -> lane l stores row b0 + (l & 7).
// L2 traffic ~5 MB/gemm; ~128 FFMA2 + 72 LDG.128 per lane.
// ---------------------------------------------------------------------------
__device__ __forceinline__ void gemm_warp(const float* __restrict__ A,
                                          const float* __restrict__ W,
                                          float* __restrict__ dst,
                                          const float* __restrict__ bias) {
    const int lane = threadIdx.x & 31;
    const int gw   = blockIdx.x * 8 + (threadIdx.x >> 5);   // 0..4095
    const int o    = gw & 1023;
    const int b0   = (gw >> 10) * 8;

    const ulonglong2* Wr = reinterpret_cast<const ulonglong2*>(W)
                         + (size_t)o * (ND4 / 2) * 2 / 2;   // = o * 256 /? keep simple below
    // index in 16B units: row o has 256 float4 = 256 ulonglong2
    Wr = reinterpret_cast<const ulonglong2*>(W) + (size_t)o * 256 + lane * 8;
    const ulonglong2* Ar = reinterpret_cast<const ulonglong2*>(A)
                         + (size_t)b0 * 256 + lane * 8;

    unsigned long long acc[8];
    #pragma unroll
    for (int b = 0; b < 8; ++b) acc[b] = 0ull;

    #pragma unroll
    for (int c = 0; c < 2; ++c) {               // two 16-float K chunks
        ulonglong2 w0 = Wr[c * 4 + 0];
        ulonglong2 w1 = Wr[c * 4 + 1];
        ulonglong2 w2 = Wr[c * 4 + 2];
        ulonglong2 w3 = Wr[c * 4 + 3];
        #pragma unroll
        for (int b = 0; b < 8; ++b) {
            const ulonglong2* ar = Ar + (size_t)b * 256 + c * 4;
            ulonglong2 a0 = ar[0], a1 = ar[1], a2 = ar[2], a3 = ar[3];
            ffma2(acc[b], a0.x, w0.x); ffma2(acc[b], a0.y, w0.y);
            ffma2(acc[b], a1.x, w1.x); ffma2(acc[b], a1.y, w1.y);
            ffma2(acc[b], a2.x, w2.x); ffma2(acc[b], a2.y, w2.y);
            ffma2(acc[b], a3.x, w3.x); ffma2(acc[b], a3.y, w3.y);
        }
    }

    float r[8];
    #pragma unroll
    for (int b = 0; b < 8; ++b) r[b] = hsum2(acc[b]);

    // Reduce over lane bits 4,3 (plain), then matched stages over bits 2,1,0.
    #pragma unroll
    for (int b = 0; b < 8; ++b) {
        r[b] += __shfl_xor_sync(0xffffffffu, r[b], 16);
        r[b] += __shfl_xor_sync(0xffffffffu, r[b], 8);
    }
#define RST(OFF)                                                           \
    {                                                                      \
        const bool up = (lane & (OFF)) != 0;                               \
        _Pragma("unroll")                                                  \
        for (int j = 0; j < (OFF); ++j) {                                  \
            float k = up ? r[j + (OFF)] : r[j];                            \
            float s = up ? r[j] : r[j + (OFF)];                            \
            r[j] = k + __shfl_xor_sync(0xffffffffu, s, (OFF));             \
        }                                                                  \
    }
    RST(4) RST(2) RST(1)
#undef RST

    if (lane < 8) {
        float v = r[0];
        if (bias != nullptr) v += bias[o];
        dst[(size_t)(b0 + lane) * ND + o] = v;
    }
}

// ---------------------------------------------------------------------------
// THE kernel: stream-reduce -> fold16 -> gemm0 -> gemm1, one launch,
// zero smem throughout (the streaming phase keeps its full L1 carveout).
// ---------------------------------------------------------------------------
__global__ void __launch_bounds__(256, 4) k_all(const float* __restrict__ x,
                                                const float* __restrict__ Wh,
                                                const float* __restrict__ Wp,
                                                const float* __restrict__ bias,
                                                float* __restrict__ out) {
    const int blk = blockIdx.x, tid = threadIdx.x;

    // Fire-and-forget W warm-up (free; helps first replay).
    {
        const unsigned g = blk * 256u + tid;     // 0..131071
        if (g < 32768u)
            l2_prefetch(reinterpret_cast<const char*>(Wh) + (size_t)g * 128);
        else if (g < 65536u)
            l2_prefetch(reinterpret_cast<const char*>(Wp) + (size_t)(g - 32768u) * 128);
    }

    // ===== Phase 0: token-sum stream reduce (R7-proven loop, untouched) ====
    {
        const int s = blk & 15, b = blk >> 4;
        const float4* xp = reinterpret_cast<const float4*>(x)
                         + ((size_t)b * NT + (size_t)s * TOK) * ND4 + tid;
        float4 a0 = make_float4(0.f, 0.f, 0.f, 0.f);
        float4 a1 = make_float4(0.f, 0.f, 0.f, 0.f);
        float4 a2 = make_float4(0.f, 0.f, 0.f, 0.f);
        float4 a3 = make_float4(0.f, 0.f, 0.f, 0.f);
        #pragma unroll 2
        for (int t = 0; t < TOK; t += 4) {
            float4 v0 = ldcs4(xp + (size_t)t * ND4);
            float4 v1 = ldcs4(xp + (size_t)(t + 1) * ND4);
            float4 v2 = ldcs4(xp + (size_t)(t + 2) * ND4);
            float4 v3 = ldcs4(xp + (size_t)(t + 3) * ND4);
            a0.x += v0.x; a0.y += v0.y; a0.z += v0.z; a0.w += v0.w;
            a1.x += v1.x; a1.y += v1.y; a1.z += v1.z; a1.w += v1.w;
            a2.x += v2.x; a2.y += v2.y; a2.z += v2.z; a2.w += v2.w;
            a3.x += v3.x; a3.y += v3.y; a3.z += v3.z; a3.w += v3.w;
        }
        float4 r = make_float4(a0.x + a1.x + a2.x + a3.x,
                               a0.y + a1.y + a2.y + a3.y,
                               a0.z + a1.z + a2.z + a3.z,
                               a0.w + a1.w + a2.w + a3.w);
        reinterpret_cast<float4*>(g_part[s])[b * ND4 + tid] = r;
    }
    grid_bar(0);

    // ===== Phase 1: fold16 -> g_xs (8192 float4 / 512 blocks = 16 each) ====
    if (tid < 16) {
        const int i = blk * 16 + tid;
        float4 v = make_float4(0.f, 0.f, 0.f, 0.f);
        #pragma unroll
        for (int s2 = 0; s2 < TS; ++s2) {
            float4 u = reinterpret_cast<const float4*>(g_part[s2])[i];
            v.x += u.x; v.y += u.y; v.z += u.z; v.w += u.w;
        }
        reinterpret_cast<float4*>(g_xs)[i] = v;
    }
    grid_bar(1);

    // ===== Phase 2: gemm0 — g_xh = xs @ Wh^T (full K, no partials) =========
    gemm_warp(g_xs, Wh, g_xh, nullptr);
    grid_bar(2);

    // ===== Phase 3: gemm1 — out = xh @ Wp^T + bias ==========================
    gemm_warp(g_xh, Wp, out, bias);
}

// ---------------------------------------------------------------------------
extern "C" void kernel_launch(void* const* d_in, const int* in_sizes, int n_in,
                              void* d_out, int out_size) {
    const float* x  = (const float*)d_in[0];   // [32, 2048, 1024]
    const float* Wh = (const float*)d_in[1];   // [16, 64, 1024] -> flat [1024,1024]
    const float* Wp = (const float*)d_in[2];   // [1024, 1024]
    const float* bp = (const float*)d_in[3];   // [1024]
    float* out = (float*)d_out;                // [32, 1024]

    k_all<<<GRID, 256>>>(x, Wh, Wp, bp, out);
}

// round 16
// speedup vs baseline: 2.0876x; 2.0876x over previous
#include <cuda_runtime.h>

#define NB 32      // batch
#define NT 2048    // tokens
#define ND 1024    // d_token == n_heads*d_head
#define ND4 (ND/4)
#define TS 16      // token splits in reduce
#define TOK (NT/TS)           // 128 tokens per reduce block
#define KS2 8      // GEMM K-splits (K-slice = 128 floats = 32 float4)
#define OT 64      // o-columns per GEMM block tile
#define RGRID 512  // reduce blocks (16 splits x 32 batch)
#define TGRID 128  // tail blocks (16 o-tiles x 8 K-splits), all wave-1

// Scratch (allocation-free: __device__ globals, zero-initialized)
__device__ float g_part[TS][NB * ND];     // reduce partials (2 MB)
__device__ float g_xs[NB * ND];           // folded token sum (128 KB)
__device__ float g_xc[KS2][NB * ND];      // GEMM1 K-split partials
__device__ float g_op[KS2][NB * ND];      // GEMM2 K-split partials
__device__ unsigned g_cnt[1];             // reduce barrier arrive counter
__device__ unsigned g_rel[1];             // reduce barrier release generation
__device__ unsigned g_flag1[8];           // gemm0 done-count per otile-pair group
__device__ unsigned g_flag2[16];          // gemm1 done-count per otile group

// ---------------------------------------------------------------------------
// Grid barrier for the reduce kernel only (512 zero-smem blocks, co-resident).
// ---------------------------------------------------------------------------
template <int GRID_N>
__device__ __forceinline__ void grid_bar(int i) {
    __syncthreads();
    if (threadIdx.x == 0) {
        volatile unsigned* rel = &g_rel[i];
        const unsigned gen = *rel;          // read BEFORE our arrive
        __threadfence();                    // publish this block's phase writes
        if (atomicAdd(&g_cnt[i], 1u) == GRID_N - 1) {
            g_cnt[i] = 0;                   // reset for next graph replay
            __threadfence();
            atomicAdd(&g_rel[i], 1u);       // release (monotone)
        } else {
            while (*rel == gen) { __nanosleep(32); }
        }
        __threadfence();
    }
    __syncthreads();
}

// ---------------------------------------------------------------------------
// helpers
// ---------------------------------------------------------------------------
__device__ __forceinline__ void ffma2(unsigned long long& d,
                                      unsigned long long a,
                                      unsigned long long b) {
    asm("fma.rn.f32x2 %0, %1, %2, %0;" : "+l"(d) : "l"(a), "l"(b));
}
__device__ __forceinline__ void lds_v2u64(unsigned long long& lo,
                                          unsigned long long& hi,
                                          unsigned addr) {
    asm volatile("ld.shared.v2.u64 {%0, %1}, [%2];"
                 : "=l"(lo), "=l"(hi) : "r"(addr));
}
__device__ __forceinline__ float hsum2(unsigned long long v) {
    float2 f;
    __builtin_memcpy(&f, &v, 8);
    return f.x + f.y;
}
__device__ __forceinline__ float4 ldcs4(const float4* p) {   // streaming load
    float4 v;
    asm volatile("ld.global.cs.v4.f32 {%0,%1,%2,%3}, [%4];"
                 : "=f"(v.x), "=f"(v.y), "=f"(v.z), "=f"(v.w) : "l"(p));
    return v;
}
__device__ __forceinline__ void cp16(unsigned smem_addr, const void* gptr) {
    asm volatile("cp.async.cg.shared.global [%0], [%1], 16;"
                 :: "r"(smem_addr), "l"(gptr));
}
#define CP_COMMIT() asm volatile("cp.async.commit_group;")
#define CP_WAIT(N)  asm volatile("cp.async.wait_group %0;" :: "n"(N))

// ---------------------------------------------------------------------------
// Kernel 1: token-sum reduce (R7/R14-proven, untouched core). Also resets the
// tail's producer/consumer flags (stream order makes this race-free).
// ---------------------------------------------------------------------------
__global__ void __launch_bounds__(256, 4) k_reduce(const float* __restrict__ x) {
    const int s = blockIdx.x & 15, b = blockIdx.x >> 4, j = threadIdx.x;

    if (blockIdx.x == 0 && j < 24) {        // reset tail flags for this replay
        if (j < 8) g_flag1[j] = 0;
        else       g_flag2[j - 8] = 0;
    }

    {
        const float4* xp = reinterpret_cast<const float4*>(x)
                         + ((size_t)b * NT + (size_t)s * TOK) * ND4 + j;
        float4 a0 = make_float4(0.f, 0.f, 0.f, 0.f);
        float4 a1 = make_float4(0.f, 0.f, 0.f, 0.f);
        float4 a2 = make_float4(0.f, 0.f, 0.f, 0.f);
        float4 a3 = make_float4(0.f, 0.f, 0.f, 0.f);
        #pragma unroll 2
        for (int t = 0; t < TOK; t += 4) {
            float4 v0 = ldcs4(xp + (size_t)t * ND4);
            float4 v1 = ldcs4(xp + (size_t)(t + 1) * ND4);
            float4 v2 = ldcs4(xp + (size_t)(t + 2) * ND4);
            float4 v3 = ldcs4(xp + (size_t)(t + 3) * ND4);
            a0.x += v0.x; a0.y += v0.y; a0.z += v0.z; a0.w += v0.w;
            a1.x += v1.x; a1.y += v1.y; a1.z += v1.z; a1.w += v1.w;
            a2.x += v2.x; a2.y += v2.y; a2.z += v2.z; a2.w += v2.w;
            a3.x += v3.x; a3.y += v3.y; a3.z += v3.z; a3.w += v3.w;
        }
        float4 r = make_float4(a0.x + a1.x + a2.x + a3.x,
                               a0.y + a1.y + a2.y + a3.y,
                               a0.z + a1.z + a2.z + a3.z,
                               a0.w + a1.w + a2.w + a3.w);
        reinterpret_cast<float4*>(g_part[s])[b * ND4 + j] = r;
    }
    grid_bar<RGRID>(0);
    // fold16 -> g_xs: 8192 float4 over 512 blocks = 16 per block
    if (j < 16) {
        const int i = blockIdx.x * 16 + j;
        float4 v = make_float4(0.f, 0.f, 0.f, 0.f);
        #pragma unroll
        for (int s2 = 0; s2 < TS; ++s2) {
            float4 u = reinterpret_cast<const float4*>(g_part[s2])[i];
            v.x += u.x; v.y += u.y; v.z += u.z; v.w += u.w;
        }
        reinterpret_cast<float4*>(g_xs)[i] = v;
    }
}

// ---------------------------------------------------------------------------
// GEMM compute core (proven R6-R14): As[b][d4] x Ws swizzled -> dst.
// 256 thr, tile 64o x 32b x 128K, f32x2 FFMA packed along K.
// ---------------------------------------------------------------------------
__device__ __forceinline__ void gemm_core(const float4* As, const float4* Ws,
                                          float* __restrict__ dst, int otile) {
    const int tid = threadIdx.x;
    const int ox = tid & 31;
    const int bp = tid >> 5;
    const unsigned asBase = (unsigned)__cvta_generic_to_shared(As);
    const unsigned wsBase = (unsigned)__cvta_generic_to_shared(Ws);

    unsigned long long acc[4][2];
    #pragma unroll
    for (int i = 0; i < 4; ++i) { acc[i][0] = 0ull; acc[i][1] = 0ull; }

    #pragma unroll 8
    for (int d4 = 0; d4 < 32; ++d4) {
        unsigned long long w0lo, w0hi, w1lo, w1hi;
        lds_v2u64(w0lo, w0hi, wsBase + (unsigned)((d4 * OT + ((ox + d4) & 63)) << 4));
        lds_v2u64(w1lo, w1hi, wsBase + (unsigned)((d4 * OT + ((ox + 32 + d4) & 63)) << 4));
        #pragma unroll
        for (int i = 0; i < 4; ++i) {
            unsigned long long alo, ahi;
            lds_v2u64(alo, ahi, asBase + (unsigned)((((4 * bp + i) * 32 + d4)) << 4));
            ffma2(acc[i][0], alo, w0lo);
            ffma2(acc[i][0], ahi, w0hi);
            ffma2(acc[i][1], alo, w1lo);
            ffma2(acc[i][1], ahi, w1hi);
        }
    }
    #pragma unroll
    for (int i = 0; i < 4; ++i) {
        const int b = 4 * bp + i;
        dst[b * ND + otile + ox]      = hsum2(acc[i][0]);
        dst[b * ND + otile + 32 + ox] = hsum2(acc[i][1]);
    }
}

// issue cp.async for one W tile (64o x 32d4, swizzled layout)
__device__ __forceinline__ void w_tile_cp(const float* __restrict__ W,
                                          float4* Ws, int otile, int kbase4) {
    const int tid = threadIdx.x;
    const int o = tid >> 5, d4 = tid & 31;
    const unsigned base = (unsigned)__cvta_generic_to_shared(Ws);
    #pragma unroll
    for (int r = 0; r < 8; ++r) {
        const int oo = o + r * 8;
        cp16(base + (unsigned)((d4 * OT + ((oo + d4) & 63)) << 4),
             reinterpret_cast<const float4*>(W) + (size_t)(otile + oo) * ND4 + kbase4 + d4);
    }
}

// ---------------------------------------------------------------------------
// Kernel 2: tail with NO global barriers. 128 blocks x 256 thr, 80 KB smem.
// Dependencies via fine-grained flags:
//   flag1[g]: gemm0 completions of group g = blocks 16g..16g+15 (o-tiles 2g,
//             2g+1). Consumer (·, ks) needs exactly group ks.
//   flag2[t]: gemm1 completions of o-tile t; the 8th arriver runs the
//             epilogue for tile t (fold order fixed -> deterministic).
// Every block arrives at flag1 BEFORE any block waits -> deadlock-free.
// ---------------------------------------------------------------------------
__global__ void __launch_bounds__(256) k_tail(const float* __restrict__ Wh,
                                              const float* __restrict__ Wp,
                                              const float* __restrict__ bias,
                                              float* __restrict__ out) {
    extern __shared__ float4 dynsm[];
    float4* Ws0 = dynsm;            // 2048 float4 = 32 KB (Wh tile)
    float4* Ws1 = dynsm + 2048;     // 2048 float4 = 32 KB (Wp tile)
    float4* As  = dynsm + 4096;     // 1024 float4 = 16 KB
    __shared__ unsigned s_old;
    const int tid = threadIdx.x;
    const int blk = blockIdx.x;
    const int otile  = (blk >> 3) * OT;
    const int kbase4 = (blk & 7) * 32;

    // group 0: Wh tile + A tile (xs K-slice); group 1: Wp tile (hidden later)
    w_tile_cp(Wh, Ws0, otile, kbase4);
    {
        const unsigned base = (unsigned)__cvta_generic_to_shared(As);
        #pragma unroll
        for (int k = 0; k < 4; ++k) {
            const int idx = tid + k * 256;      // 1024 = 32b x 32d4
            const int b = idx >> 5, d4 = idx & 31;
            cp16(base + (unsigned)(idx << 4),
                 reinterpret_cast<const float4*>(g_xs) + b * ND4 + kbase4 + d4);
        }
    }
    CP_COMMIT();
    w_tile_cp(Wp, Ws1, otile, kbase4);
    CP_COMMIT();

    CP_WAIT(1);
    __syncthreads();

    // Phase 1: gemm0 — g_xc[ks] = xs @ Wh^T, then release into flag1.
    gemm_core(As, Ws0, g_xc[blk & 7], otile);
    __threadfence();                 // each thread publishes its own stores
    __syncthreads();
    if (tid == 0) atomicAdd(&g_flag1[blk >> 4], 1u);

    // Wait ONLY for the 16 producers of my A-slice (o-tiles 2ks, 2ks+1).
    if (tid == 0) {
        volatile unsigned* f = &g_flag1[blk & 7];
        while (*f < 16u) { __nanosleep(32); }
    }
    __syncthreads();

    // Phase 2: fold8 A from g_xc, then gemm1 with prefetched Wp tile.
    {
        #pragma unroll
        for (int k = 0; k < 4; ++k) {
            const int idx = tid + k * 256;
            const int b = idx >> 5, d4 = idx & 31;
            float4 v = make_float4(0.f, 0.f, 0.f, 0.f);
            #pragma unroll
            for (int p = 0; p < KS2; ++p) {
                float4 u = reinterpret_cast<const float4*>(g_xc[p])[b * ND4 + kbase4 + d4];
                v.x += u.x; v.y += u.y; v.z += u.z; v.w += u.w;
            }
            As[idx] = v;
        }
    }
    CP_WAIT(0);
    __syncthreads();
    gemm_core(As, Ws1, g_op[blk & 7], otile);
    __threadfence();
    __syncthreads();

    // Arrive at flag2[otile]; the LAST (8th) arriver runs that tile's epilogue.
    if (tid == 0) s_old = atomicAdd(&g_flag2[blk >> 3], 1u);
    __syncthreads();
    if (s_old == 7u) {
        // out[b, otile..otile+63] = sum_p g_op[p][b,c] + bias[c]
        #pragma unroll
        for (int r = 0; r < 8; ++r) {
            const int idx = tid + r * 256;      // 0..2047
            const int b = idx >> 6;
            const int c = otile + (idx & 63);
            float acc = bias[c];
            #pragma unroll
            for (int p = 0; p < KS2; ++p) acc += g_op[p][b * ND + c];
            out[b * ND + c] = acc;
        }
    }
}

// ---------------------------------------------------------------------------
extern "C" void kernel_launch(void* const* d_in, const int* in_sizes, int n_in,
                              void* d_out, int out_size) {
    const float* x  = (const float*)d_in[0];   // [32, 2048, 1024]
    const float* Wh = (const float*)d_in[1];   // [16, 64, 1024] -> flat [1024,1024]
    const float* Wp = (const float*)d_in[2];   // [1024, 1024]
    const float* bp = (const float*)d_in[3];   // [1024]
    float* out = (float*)d_out;                // [32, 1024]

    static int once = 0;
    if (!once) {
        cudaFuncSetAttribute(k_tail, cudaFuncAttributeMaxDynamicSharedMemorySize,
                             5120 * sizeof(float4));
        once = 1;
    }
    k_reduce<<<RGRID, 256>>>(x);
    k_tail<<<TGRID, 256, 5120 * sizeof(float4)>>>(Wh, Wp, bp, out);
}